// round 8
// baseline (speedup 1.0000x reference)
#include <cuda_runtime.h>
#include <math.h>

#define NS_   6
#define NT_   4
#define B_    2
#define N_    32
#define H_    768
#define W_    768
#define ROI_  28
#define C_    10           // NS + NT
#define L_    39           // 1 + NS + N
#define NEGV  (-100.0f)

#define SEAM_TOT (B_ * H_ * W_)                 // 1179648
#define FULL_OUT (SEAM_TOT + 2 * B_ * L_ + B_)  // 1179806
#define LUTN  (NS_ + N_)                        // 38

struct BoxP {
    int y0i, x0i, y1r, x1r;   // strict box (exclusive upper)
    int ys, ye, xs, xe;       // mask box (exclusive upper); subset of strict box
    float ry, rx;             // 28/h, 28/w
    int clsN;                 // thing class 0..3
    int mskoff;               // offset into roi_msk for (b,n,cls)
};

__device__ BoxP g_box[B_ * N_];
__device__ int g_hist[B_ * N_ * C_];
__device__ int g_cstuff[B_ * NS_];
__device__ __align__(16) unsigned char g_pp[B_ * H_ * W_];
__device__ float g_lutf[B_ * LUTN];

// XLA logistic_expander form: 1 / (1 + exp(-x)). sigmoid(-100) == 0 exactly.
__device__ __forceinline__ float jsig(float x) {
    return __fdiv_rn(1.0f, __fadd_rn(1.0f, expf(-x)));
}

// ---- kernel 0: zero scratch + residual out, precompute boxes ---------------
__global__ void __launch_bounds__(256)
k_fill(const float* __restrict__ bbx, const int* __restrict__ cls,
       float* __restrict__ out, int out_size) {
    int t = threadIdx.x;
    for (int i = t; i < B_ * N_ * C_; i += 256) g_hist[i] = 0;
    for (int i = t; i < B_ * NS_; i += 256) g_cstuff[i] = 0;
    for (int i = FULL_OUT + t; i < out_size; i += 256) out[i] = 0.0f;

    if (t < B_ * N_) {
        int b = t / N_, n = t % N_;
        const float* bb = bbx + t * 4;
        float y0f = bb[0], x0f = bb[1], y1f = bb[2], x1f = bb[3];
        int y0 = (int)floorf(y0f), x0 = (int)floorf(x0f);
        int y1 = (int)floorf(y1f), x1 = (int)floorf(x1f);
        int y1r = (int)(rintf(y1f) + 1.0f);   // round-half-even
        int x1r = (int)(rintf(x1f) + 1.0f);
        int hi = y1 - y0 + 1; if (hi < 1) hi = 1;
        int wi = x1 - x0 + 1; if (wi < 1) wi = 1;
        BoxP bp;
        bp.y0i = y0; bp.x0i = x0; bp.y1r = y1r; bp.x1r = x1r;
        bp.ys = max(y0, 0); bp.ye = min(y1 + 1, H_);
        bp.xs = max(x0, 0); bp.xe = min(x1 + 1, W_);
        bp.ry = __fdiv_rn(28.0f, (float)hi);
        bp.rx = __fdiv_rn(28.0f, (float)wi);
        int c = cls[t];
        bp.clsN = c;
        bp.mskoff = ((b * N_ + n) * NT_ + c) * ROI_ * ROI_;
        g_box[t] = bp;
    }
}

// ---- kernel 1: fused per-pixel argmax + histograms -------------------------
// 192 threads x 4 px (float4 channel loads). Row-active instances compacted;
// per-warp ballot narrows to instances meeting the warp's 128-px window.
// Non-covering instances contribute C_OUT=-0.0 exactly (gap logic preserves
// argmax-first ordering). Histogram updates warp-aggregated via match_any.
__global__ void __launch_bounds__(192)
k_main(const float* __restrict__ sem, const float* __restrict__ roi) {
    const int y = blockIdx.x;
    const int b = blockIdx.y;
    const int t = threadIdx.x;
    const int lane = t & 31;

    __shared__ int sh_hist[N_ * C_];
    __shared__ int sh_cst[NS_];
    __shared__ int sh_K;
    __shared__ int sa_n[N_], sa_x0[N_], sa_x1r[N_], sa_xs[N_], sa_xe[N_];
    __shared__ int sa_inYm[N_], sa_cls[N_], sa_r0[N_], sa_r1[N_];
    __shared__ float sa_wy[N_], sa_rx[N_];

    for (int i = t; i < N_ * C_; i += 192) sh_hist[i] = 0;
    if (t < NS_) sh_cst[t] = 0;

    if (t < 32) {
        BoxP bp = g_box[b * N_ + t];
        bool inYs = (y >= bp.y0i) && (y < bp.y1r);
        unsigned mask = __ballot_sync(0xffffffffu, inYs);
        if (t == 0) sh_K = __popc(mask);
        if (inYs) {
            int slot = __popc(mask & ((1u << t) - 1u));
            sa_n[slot] = t;
            sa_x0[slot] = bp.x0i; sa_x1r[slot] = bp.x1r;
            sa_xs[slot] = bp.xs;  sa_xe[slot] = bp.xe;
            sa_cls[slot] = bp.clsN; sa_rx[slot] = bp.rx;
            int inYm = (y >= bp.ys) && (y < bp.ye);
            sa_inYm[slot] = inYm;
            if (inYm) {
                float sy = __fsub_rn(
                    __fmul_rn(__fadd_rn(__fsub_rn((float)y, (float)bp.y0i), 0.5f), bp.ry),
                    0.5f);
                sy = fminf(fmaxf(sy, 0.0f), 27.0f);
                float fiy0 = floorf(sy);
                int iy0 = (int)fiy0;
                int iy1 = min(iy0 + 1, ROI_ - 1);
                sa_wy[slot] = __fsub_rn(sy, fiy0);
                sa_r0[slot] = bp.mskoff + iy0 * ROI_;
                sa_r1[slot] = bp.mskoff + iy1 * ROI_;
            } else {
                sa_wy[slot] = 0.0f; sa_r0[slot] = 0; sa_r1[slot] = 0;
            }
        }
    }
    __syncthreads();

    const int K = sh_K;
    const float C_OUT = -0.0f;
    const float* semb0 = sem + (size_t)b * (C_ * H_ * W_) + (size_t)y * W_;

    // warp window: warp w covers pixels [w*128, w*128+128)
    unsigned wmask;
    {
        int wlo = (t & ~31) * 4;
        bool inter = false;
        if (lane < K) inter = (sa_x0[lane] <= wlo + 127) && (sa_x1r[lane] > wlo);
        wmask = __ballot_sync(0xffffffffu, inter);
    }

    // vectorized channel loads: 4 consecutive pixels per thread
    float4 s4[C_];
#pragma unroll
    for (int c = 0; c < C_; c++)
        s4[c] = __ldg((const float4*)(semb0 + (size_t)c * (H_ * W_)) + t);

#pragma unroll
    for (int j = 0; j < 4; j++) {
        const int x = t * 4 + j;
        float s[C_];
#pragma unroll
        for (int c = 0; c < C_; c++)
            s[c] = (j == 0) ? s4[c].x : (j == 1) ? s4[c].y : (j == 2) ? s4[c].z : s4[c].w;

        int sem_pred = 0; float sb = s[0];
#pragma unroll
        for (int c = 1; c < C_; c++) if (s[c] > sb) { sb = s[c]; sem_pred = c; }

        float best = s[0]; int bi = 0;
#pragma unroll
        for (int c = 1; c < NS_; c++) if (s[c] > best) { best = s[c]; bi = c; }

        int nextn = 0;
        for (unsigned mrem = wmask; mrem; mrem &= mrem - 1) {
            int k = __ffs(mrem) - 1;
            int n = sa_n[k];
            if (n > nextn && best < 0.0f) { best = C_OUT; bi = NS_ + nextn; }
            nextn = n + 1;

            float v;
            bool sxin = (x >= sa_x0[k]) && (x < sa_x1r[k]);
            if (!sxin) {
                v = C_OUT;
            } else {
                float a = s[NS_ + sa_cls[k]];
                float m;
                bool mxin = sa_inYm[k] && (x >= sa_xs[k]) && (x < sa_xe[k]);
                if (mxin) {
                    float sx = __fsub_rn(
                        __fmul_rn(__fadd_rn(__fsub_rn((float)x, (float)sa_x0[k]), 0.5f),
                                  sa_rx[k]),
                        0.5f);
                    sx = fminf(fmaxf(sx, 0.0f), 27.0f);
                    float fix0 = floorf(sx);
                    int ix0 = (int)fix0;
                    int ix1 = min(ix0 + 1, ROI_ - 1);
                    float wx = __fsub_rn(sx, fix0);
                    const float* r0 = roi + sa_r0[k];
                    const float* r1 = roi + sa_r1[k];
                    float wy = sa_wy[k];
                    float omy = __fsub_rn(1.0f, wy);
                    float c0 = __fadd_rn(__fmul_rn(__ldg(r0 + ix0), omy),
                                         __fmul_rn(__ldg(r1 + ix0), wy));
                    float c1 = __fadd_rn(__fmul_rn(__ldg(r0 + ix1), omy),
                                         __fmul_rn(__ldg(r1 + ix1), wy));
                    float omx = __fsub_rn(1.0f, wx);
                    m = __fadd_rn(__fmul_rn(c0, omx), __fmul_rn(c1, wx));
                } else {
                    m = NEGV;
                }
                v = __fmul_rn(__fadd_rn(jsig(a), jsig(m)), __fadd_rn(a, m));
            }
            if (v > best) { best = v; bi = NS_ + n; }
        }
        if (nextn < N_ && best < 0.0f) { best = C_OUT; bi = NS_ + nextn; }

        g_pp[((size_t)b * H_ + y) * W_ + x] = (unsigned char)bi;

        // warp-aggregated histogram update
        int key = (bi >= NS_) ? (64 + (bi - NS_) * C_ + sem_pred) : bi;
        unsigned mm = __match_any_sync(0xffffffffu, key);
        if (lane == __ffs(mm) - 1) {
            int cnt = __popc(mm);
            if (key >= 64) atomicAdd(&sh_hist[key - 64], cnt);
            else           atomicAdd(&sh_cst[key], cnt);
        }
    }
    __syncthreads();

    for (int i = t; i < N_ * C_; i += 192) {
        int v = sh_hist[i];
        if (v) atomicAdd(&g_hist[b * N_ * C_ + i], v);
    }
    if (t < NS_) {
        int v = sh_cst[t];
        if (v) atomicAdd(&g_cstuff[b * NS_ + t], v);
    }
}

// ---- kernel 2: warp-parallel relabel + small outputs (1 warp per batch) ----
__global__ void __launch_bounds__(64)
k_post(const int* __restrict__ cls, float* __restrict__ out, int out_size) {
    const unsigned FULL = 0xffffffffu;
    int b = threadIdx.x >> 5;
    int lane = threadIdx.x & 31;
    const int* hist = g_hist + (b * N_ + lane) * C_;

    int tot = 0, mc = 0, smax = 0;
#pragma unroll
    for (int c = 0; c < C_; c++) {
        int h = hist[c];
        tot += h;
        if (h > mc) { mc = h; smax = c; }
    }
    int pres = (tot > 0);
    int tmp = cls[b * N_ + lane] + NS_;
    int br1 = (smax == tmp);
    int br2 = (!br1) && (2 * mc >= tot) && (smax < NS_) && pres;
    int semlab = br2 ? smax : tmp;
    int kept = pres && !br2;

    int sp[NS_];
#pragma unroll
    for (int c = 0; c < NS_; c++) {
        int v = (semlab == c) ? tot : 0;
#pragma unroll
        for (int off = 16; off; off >>= 1) v += __shfl_down_sync(FULL, v, off);
        v = __shfl_sync(FULL, v, 0);
        sp[c] = g_cstuff[b * NS_ + c] + v;
    }

    int srank[NS_], nst = 0;
#pragma unroll
    for (int c = 0; c < NS_; c++) { if (sp[c] > 0) nst++; srank[c] = nst - 1; }

    unsigned kb = __ballot_sync(FULL, kept);
    int rank_k = __popc(kb & ((1u << lane) - 1u));
    int rk = __popc(kb);

    float* lut = g_lutf + b * LUTN;
    if (lane < NS_) lut[lane] = (float)(srank[lane] + 1);
    int lv = kept ? (1 + nst + rank_k)
                  : ((semlab < NS_) ? (srank[semlab] + 1) : 0);
    lut[NS_ + lane] = (float)lv;

    if (out_size >= FULL_OUT) {
        float* pcls = out + SEAM_TOT + b * L_;
        float* pisc = out + SEAM_TOT + B_ * L_ + b * L_;
        pcls[lane] = -1.0f;
        if (lane < L_ - 32) pcls[32 + lane] = -1.0f;
        __syncwarp(FULL);
        if (lane == 0) pcls[0] = 255.0f;
        if (lane < NS_ && sp[lane] > 0) pcls[1 + srank[lane]] = (float)lane;
        if (kept) pcls[1 + nst + rank_k] = (float)tmp;
        int vl = 1 + nst + rk;
        pisc[lane] = (lane < vl) ? 0.0f : -1.0f;
        if (lane < L_ - 32) pisc[32 + lane] = ((32 + lane) < vl) ? 0.0f : -1.0f;
        if (lane == 0) out[SEAM_TOT + 2 * B_ * L_ + b] = (float)vl;
    }
}

// ---- kernel 3: LUT remap; shared LUT, 2 quads/thread, 576 blocks -----------
__global__ void __launch_bounds__(256)
k_out(float* __restrict__ out) {
    __shared__ float lut[B_ * LUTN];
    int t = threadIdx.x;
    if (t < B_ * LUTN) lut[t] = g_lutf[t];
    __syncthreads();
    const int HWQ = H_ * W_ / 4;
    int base = blockIdx.x * 512 + t;
#pragma unroll
    for (int j = 0; j < 2; j++) {
        int i = base + j * 256;
        unsigned int p = ((const unsigned int*)g_pp)[i];
        const float* l = lut + ((i >= HWQ) ? LUTN : 0);
        float4 o;
        o.x = l[p & 0xFF];
        o.y = l[(p >> 8) & 0xFF];
        o.z = l[(p >> 16) & 0xFF];
        o.w = l[(p >> 24) & 0xFF];
        ((float4*)out)[i] = o;
    }
}

extern "C" void kernel_launch(void* const* d_in, const int* in_sizes, int n_in,
                              void* d_out, int out_size) {
    const float* sem = nullptr;
    const float* roi = nullptr;
    const float* bbx = nullptr;
    const int*   cls = nullptr;
    for (int i = 0; i < n_in; i++) {
        long long s = in_sizes[i];
        if (s >= 4000000)                 sem = (const float*)d_in[i];
        else if (s >= 100000)             roi = (const float*)d_in[i];
        else if (s >= 512 && s <= 4096)   bbx = (const float*)d_in[i];
        else if (s == 256) { if (!bbx) bbx = (const float*)d_in[i]; }
        else if (s <= 255)                cls = (const int*)d_in[i];
    }
    if (!sem) sem = (const float*)d_in[0];
    if (!roi) roi = (const float*)d_in[1];
    if (!bbx) bbx = (const float*)d_in[2];
    if (!cls) cls = (const int*)d_in[3];

    float* out = (float*)d_out;

    k_fill<<<1, 256>>>(bbx, cls, out, out_size);
    dim3 g1(H_, B_);
    k_main<<<g1, 192>>>(sem, roi);
    k_post<<<1, 64>>>(cls, out, out_size);
    k_out<<<SEAM_TOT / 4 / 512, 256>>>(out);   // 576 blocks
}

// round 9
// speedup vs baseline: 1.5140x; 1.5140x over previous
#include <cuda_runtime.h>
#include <math.h>

#define NS_   6
#define NT_   4
#define B_    2
#define N_    32
#define H_    768
#define W_    768
#define ROI_  28
#define C_    10           // NS + NT
#define L_    39           // 1 + NS + N
#define NEGV  (-100.0f)

#define SEAM_TOT (B_ * H_ * W_)                 // 1179648
#define FULL_OUT (SEAM_TOT + 2 * B_ * L_ + B_)  // 1179806
#define LUTN  (NS_ + N_)                        // 38

// Scratch: zero-initialized at module load; k_post re-zeroes hist/cstuff after
// consuming them, so every graph replay starts clean (self-cleaning pipeline).
__device__ int g_hist[B_ * N_ * C_];
__device__ int g_cstuff[B_ * NS_];
__device__ __align__(16) unsigned char g_pp[B_ * H_ * W_];
__device__ float g_lutf[B_ * LUTN];

// XLA logistic_expander form: 1 / (1 + exp(-x)). sigmoid(-100) == 0 exactly.
__device__ __forceinline__ float jsig(float x) {
    return __fdiv_rn(1.0f, __fadd_rn(1.0f, expf(-x)));
}

// ---- kernel 1: fused per-pixel argmax + histograms -------------------------
// One block per (row, batch); 256 thr x 3 px. Box params computed in-block
// (t<32) straight from bbx/cls. Row-active instances compacted; per
// (warp, 256-px tile) ballot narrows to instances meeting the warp's 32-px
// window. Non-covering instances contribute C_OUT = -0.0 exactly, applied at
// the first skipped index (argmax-first ordering preserved). Histogram updates
// are warp-aggregated via match_any (kills ATOMS 32-way serialization).
__global__ void __launch_bounds__(256)
k_main(const float* __restrict__ sem, const float* __restrict__ roi,
       const float* __restrict__ bbx, const int* __restrict__ cls) {
    const int y = blockIdx.x;
    const int b = blockIdx.y;
    const int t = threadIdx.x;
    const int lane = t & 31;

    __shared__ int sh_hist[N_ * C_];
    __shared__ int sh_cst[NS_];
    __shared__ int sh_K;
    __shared__ int sa_n[N_], sa_x0[N_], sa_x1r[N_], sa_xs[N_], sa_xe[N_];
    __shared__ int sa_inYm[N_], sa_cls[N_], sa_r0[N_], sa_r1[N_];
    __shared__ float sa_wy[N_], sa_rx[N_];

    for (int i = t; i < N_ * C_; i += 256) sh_hist[i] = 0;
    if (t < NS_) sh_cst[t] = 0;

    if (t < 32) {
        // per-instance box precompute (from global inputs, ~20 ops/thread)
        const float* bb = bbx + (b * N_ + t) * 4;
        float y0f = bb[0], x0f = bb[1], y1f = bb[2], x1f = bb[3];
        int y0 = (int)floorf(y0f), x0 = (int)floorf(x0f);
        int y1 = (int)floorf(y1f), x1 = (int)floorf(x1f);
        int y1r = (int)(rintf(y1f) + 1.0f);   // round-half-even like jnp.round
        int x1r = (int)(rintf(x1f) + 1.0f);
        int hi = y1 - y0 + 1; if (hi < 1) hi = 1;
        int wi = x1 - x0 + 1; if (wi < 1) wi = 1;
        int ys = max(y0, 0), ye = min(y1 + 1, H_);
        float ry = __fdiv_rn(28.0f, (float)hi);
        float rx = __fdiv_rn(28.0f, (float)wi);
        int c = cls[b * N_ + t];
        int mskoff = ((b * N_ + t) * NT_ + c) * ROI_ * ROI_;

        bool inYs = (y >= y0) && (y < y1r);
        unsigned mask = __ballot_sync(0xffffffffu, inYs);
        if (t == 0) sh_K = __popc(mask);
        if (inYs) {
            int slot = __popc(mask & ((1u << t) - 1u));
            sa_n[slot] = t;
            sa_x0[slot] = x0; sa_x1r[slot] = x1r;
            sa_xs[slot] = max(x0, 0); sa_xe[slot] = min(x1 + 1, W_);
            sa_cls[slot] = c; sa_rx[slot] = rx;
            int inYm = (y >= ys) && (y < ye);
            sa_inYm[slot] = inYm;
            if (inYm) {
                float sy = __fsub_rn(
                    __fmul_rn(__fadd_rn(__fsub_rn((float)y, (float)y0), 0.5f), ry),
                    0.5f);
                sy = fminf(fmaxf(sy, 0.0f), 27.0f);
                float fiy0 = floorf(sy);
                int iy0 = (int)fiy0;
                int iy1 = min(iy0 + 1, ROI_ - 1);
                sa_wy[slot] = __fsub_rn(sy, fiy0);
                sa_r0[slot] = mskoff + iy0 * ROI_;
                sa_r1[slot] = mskoff + iy1 * ROI_;
            } else {
                sa_wy[slot] = 0.0f; sa_r0[slot] = 0; sa_r1[slot] = 0;
            }
        }
    }
    __syncthreads();

    const int K = sh_K;
    const float C_OUT = -0.0f;
    const float* semb0 = sem + (size_t)b * (C_ * H_ * W_) + (size_t)y * W_;

    for (int px = 0; px < W_ / 256; px++) {
        const int x = t + px * 256;

        // warp filter: instances whose strict x-interval meets this warp's
        // 32-pixel window
        unsigned wmask;
        {
            int wlo = px * 256 + (t & ~31);
            bool inter = false;
            if (lane < K) inter = (sa_x0[lane] <= wlo + 31) && (sa_x1r[lane] > wlo);
            wmask = __ballot_sync(0xffffffffu, inter);
        }

        float s[C_];
#pragma unroll
        for (int c = 0; c < C_; c++) s[c] = __ldg(semb0 + (size_t)c * (H_ * W_) + x);

        int sem_pred = 0; float sb = s[0];
#pragma unroll
        for (int c = 1; c < C_; c++) if (s[c] > sb) { sb = s[c]; sem_pred = c; }

        float best = s[0]; int bi = 0;
#pragma unroll
        for (int c = 1; c < NS_; c++) if (s[c] > best) { best = s[c]; bi = c; }

        int nextn = 0;
        for (unsigned mrem = wmask; mrem; mrem &= mrem - 1) {
            int k = __ffs(mrem) - 1;
            int n = sa_n[k];
            if (n > nextn && best < 0.0f) { best = C_OUT; bi = NS_ + nextn; }
            nextn = n + 1;

            float v;
            bool sxin = (x >= sa_x0[k]) && (x < sa_x1r[k]);
            if (!sxin) {
                v = C_OUT;
            } else {
                float a = s[NS_ + sa_cls[k]];
                float m;
                bool mxin = sa_inYm[k] && (x >= sa_xs[k]) && (x < sa_xe[k]);
                if (mxin) {
                    float sx = __fsub_rn(
                        __fmul_rn(__fadd_rn(__fsub_rn((float)x, (float)sa_x0[k]), 0.5f),
                                  sa_rx[k]),
                        0.5f);
                    sx = fminf(fmaxf(sx, 0.0f), 27.0f);
                    float fix0 = floorf(sx);
                    int ix0 = (int)fix0;
                    int ix1 = min(ix0 + 1, ROI_ - 1);
                    float wx = __fsub_rn(sx, fix0);
                    const float* r0 = roi + sa_r0[k];
                    const float* r1 = roi + sa_r1[k];
                    float wy = sa_wy[k];
                    float omy = __fsub_rn(1.0f, wy);
                    float c0 = __fadd_rn(__fmul_rn(__ldg(r0 + ix0), omy),
                                         __fmul_rn(__ldg(r1 + ix0), wy));
                    float c1 = __fadd_rn(__fmul_rn(__ldg(r0 + ix1), omy),
                                         __fmul_rn(__ldg(r1 + ix1), wy));
                    float omx = __fsub_rn(1.0f, wx);
                    m = __fadd_rn(__fmul_rn(c0, omx), __fmul_rn(c1, wx));
                } else {
                    m = NEGV;
                }
                v = __fmul_rn(__fadd_rn(jsig(a), jsig(m)), __fadd_rn(a, m));
            }
            if (v > best) { best = v; bi = NS_ + n; }
        }
        if (nextn < N_ && best < 0.0f) { best = C_OUT; bi = NS_ + nextn; }

        g_pp[((size_t)b * H_ + y) * W_ + x] = (unsigned char)bi;

        // warp-aggregated histogram update (uniform-bin common case: 1 atomic)
        int key = (bi >= NS_) ? (64 + (bi - NS_) * C_ + sem_pred) : bi;
        unsigned mm = __match_any_sync(0xffffffffu, key);
        if (lane == __ffs(mm) - 1) {
            int cnt = __popc(mm);
            if (key >= 64) atomicAdd(&sh_hist[key - 64], cnt);
            else           atomicAdd(&sh_cst[key], cnt);
        }
    }
    __syncthreads();

    for (int i = t; i < N_ * C_; i += 256) {
        int v = sh_hist[i];
        if (v) atomicAdd(&g_hist[b * N_ * C_ + i], v);
    }
    if (t < NS_) {
        int v = sh_cst[t];
        if (v) atomicAdd(&g_cstuff[b * NS_ + t], v);
    }
}

// ---- kernel 2: warp-parallel relabel + small outputs; self-cleans scratch --
__global__ void __launch_bounds__(64)
k_post(const int* __restrict__ cls, float* __restrict__ out, int out_size) {
    const unsigned FULL = 0xffffffffu;
    int b = threadIdx.x >> 5;
    int lane = threadIdx.x & 31;
    int* hist = g_hist + (b * N_ + lane) * C_;

    int tot = 0, mc = 0, smax = 0;
#pragma unroll
    for (int c = 0; c < C_; c++) {
        int h = hist[c];
        tot += h;
        if (h > mc) { mc = h; smax = c; }
    }
    int pres = (tot > 0);
    int tmp = cls[b * N_ + lane] + NS_;
    int br1 = (smax == tmp);
    int br2 = (!br1) && (2 * mc >= tot) && (smax < NS_) && pres;
    int semlab = br2 ? smax : tmp;
    int kept = pres && !br2;

    int sp[NS_];
#pragma unroll
    for (int c = 0; c < NS_; c++) {
        int v = (semlab == c) ? tot : 0;
#pragma unroll
        for (int off = 16; off; off >>= 1) v += __shfl_down_sync(FULL, v, off);
        v = __shfl_sync(FULL, v, 0);
        sp[c] = g_cstuff[b * NS_ + c] + v;
    }

    int srank[NS_], nst = 0;
#pragma unroll
    for (int c = 0; c < NS_; c++) { if (sp[c] > 0) nst++; srank[c] = nst - 1; }

    unsigned kb = __ballot_sync(FULL, kept);
    int rank_k = __popc(kb & ((1u << lane) - 1u));
    int rk = __popc(kb);

    float* lut = g_lutf + b * LUTN;
    if (lane < NS_) lut[lane] = (float)(srank[lane] + 1);
    int lv = kept ? (1 + nst + rank_k)
                  : ((semlab < NS_) ? (srank[semlab] + 1) : 0);
    lut[NS_ + lane] = (float)lv;

    if (out_size >= FULL_OUT) {
        float* pcls = out + SEAM_TOT + b * L_;
        float* pisc = out + SEAM_TOT + B_ * L_ + b * L_;
        pcls[lane] = -1.0f;
        if (lane < L_ - 32) pcls[32 + lane] = -1.0f;
        __syncwarp(FULL);
        if (lane == 0) pcls[0] = 255.0f;
        if (lane < NS_ && sp[lane] > 0) pcls[1 + srank[lane]] = (float)lane;
        if (kept) pcls[1 + nst + rank_k] = (float)tmp;
        int vl = 1 + nst + rk;
        pisc[lane] = (lane < vl) ? 0.0f : -1.0f;
        if (lane < L_ - 32) pisc[32 + lane] = ((32 + lane) < vl) ? 0.0f : -1.0f;
        if (lane == 0) out[SEAM_TOT + 2 * B_ * L_ + b] = (float)vl;
    }
    // zero any residual output beyond the defined region (usually empty loop)
    for (int i = FULL_OUT + threadIdx.x; i < out_size; i += 64) out[i] = 0.0f;

    // self-clean scratch for the next graph replay
#pragma unroll
    for (int c = 0; c < C_; c++) hist[c] = 0;
    if (lane < NS_) g_cstuff[b * NS_ + lane] = 0;
}

// ---- kernel 3: LUT remap; shared LUT, 1 quad/thread, 1152 blocks -----------
__global__ void __launch_bounds__(256)
k_out(float* __restrict__ out) {
    __shared__ float lut[B_ * LUTN];
    int t = threadIdx.x;
    if (t < B_ * LUTN) lut[t] = g_lutf[t];
    __syncthreads();
    int i = blockIdx.x * 256 + t;              // quad index
    const int HWQ = H_ * W_ / 4;
    unsigned int p = ((const unsigned int*)g_pp)[i];
    const float* l = lut + ((i >= HWQ) ? LUTN : 0);
    float4 o;
    o.x = l[p & 0xFF];
    o.y = l[(p >> 8) & 0xFF];
    o.z = l[(p >> 16) & 0xFF];
    o.w = l[(p >> 24) & 0xFF];
    ((float4*)out)[i] = o;
}

extern "C" void kernel_launch(void* const* d_in, const int* in_sizes, int n_in,
                              void* d_out, int out_size) {
    const float* sem = nullptr;
    const float* roi = nullptr;
    const float* bbx = nullptr;
    const int*   cls = nullptr;
    for (int i = 0; i < n_in; i++) {
        long long s = in_sizes[i];
        if (s >= 4000000)                 sem = (const float*)d_in[i];
        else if (s >= 100000)             roi = (const float*)d_in[i];
        else if (s >= 512 && s <= 4096)   bbx = (const float*)d_in[i];
        else if (s == 256) { if (!bbx) bbx = (const float*)d_in[i]; }
        else if (s <= 255)                cls = (const int*)d_in[i];
    }
    if (!sem) sem = (const float*)d_in[0];
    if (!roi) roi = (const float*)d_in[1];
    if (!bbx) bbx = (const float*)d_in[2];
    if (!cls) cls = (const int*)d_in[3];

    float* out = (float*)d_out;

    dim3 g1(H_, B_);
    k_main<<<g1, 256>>>(sem, roi, bbx, cls);
    k_post<<<1, 64>>>(cls, out, out_size);
    k_out<<<SEAM_TOT / 4 / 256, 256>>>(out);   // 1152 blocks
}

// round 10
// speedup vs baseline: 1.6531x; 1.0918x over previous
#include <cuda_runtime.h>
#include <math.h>

#define NS_   6
#define NT_   4
#define B_    2
#define N_    32
#define H_    768
#define W_    768
#define ROI_  28
#define C_    10           // NS + NT
#define L_    39           // 1 + NS + N
#define NEGV  (-100.0f)

#define SEAM_TOT (B_ * H_ * W_)                 // 1179648
#define FULL_OUT (SEAM_TOT + 2 * B_ * L_ + B_)  // 1179806
#define LUTN  (NS_ + N_)                        // 38

// Scratch: zero-initialized at module load; k_post re-zeroes hist/cstuff after
// consuming them, so every graph replay starts clean (self-cleaning pipeline).
__device__ int g_hist[B_ * N_ * C_];
__device__ int g_cstuff[B_ * NS_];
__device__ __align__(16) unsigned char g_pp[B_ * H_ * W_];
__device__ float g_lutf[B_ * LUTN];

// XLA logistic_expander form: 1 / (1 + exp(-x)). sigmoid(-100) == 0 exactly.
__device__ __forceinline__ float jsig(float x) {
    return __fdiv_rn(1.0f, __fadd_rn(1.0f, expf(-x)));
}

// ---- kernel 1: fused per-pixel argmax + histograms -------------------------
// One block per (row, batch); 256 thr x 3 px; forced 6 blocks/SM for occupancy.
// Box params computed in-block (t<32). Row-active instances compacted; per
// (warp, 256-px tile) ballot narrows to instances meeting the warp's 32-px
// window. Non-covering instances contribute C_OUT = -0.0 exactly, applied at
// the first skipped index (argmax-first order preserved). Stuff argmax is a
// prefix of the sem argmax (single fused scan). Histogram updates are
// warp-aggregated via match_any.
__global__ void __launch_bounds__(256, 6)
k_main(const float* __restrict__ sem, const float* __restrict__ roi,
       const float* __restrict__ bbx, const int* __restrict__ cls) {
    const int y = blockIdx.x;
    const int b = blockIdx.y;
    const int t = threadIdx.x;
    const int lane = t & 31;

    __shared__ int sh_hist[N_ * C_];
    __shared__ int sh_cst[NS_];
    __shared__ int sh_K;
    __shared__ int sa_n[N_], sa_x0[N_], sa_x1r[N_], sa_xs[N_], sa_xe[N_];
    __shared__ int sa_inYm[N_], sa_cls[N_], sa_r0[N_], sa_r1[N_];
    __shared__ float sa_wy[N_], sa_rx[N_];

    for (int i = t; i < N_ * C_; i += 256) sh_hist[i] = 0;
    if (t < NS_) sh_cst[t] = 0;

    if (t < 32) {
        const float* bb = bbx + (b * N_ + t) * 4;
        float y0f = bb[0], x0f = bb[1], y1f = bb[2], x1f = bb[3];
        int y0 = (int)floorf(y0f), x0 = (int)floorf(x0f);
        int y1 = (int)floorf(y1f), x1 = (int)floorf(x1f);
        int y1r = (int)(rintf(y1f) + 1.0f);   // round-half-even like jnp.round
        int x1r = (int)(rintf(x1f) + 1.0f);
        int hi = y1 - y0 + 1; if (hi < 1) hi = 1;
        int wi = x1 - x0 + 1; if (wi < 1) wi = 1;
        int ys = max(y0, 0), ye = min(y1 + 1, H_);
        float ry = __fdiv_rn(28.0f, (float)hi);
        float rx = __fdiv_rn(28.0f, (float)wi);
        int c = cls[b * N_ + t];
        int mskoff = ((b * N_ + t) * NT_ + c) * ROI_ * ROI_;

        bool inYs = (y >= y0) && (y < y1r);
        unsigned mask = __ballot_sync(0xffffffffu, inYs);
        if (t == 0) sh_K = __popc(mask);
        if (inYs) {
            int slot = __popc(mask & ((1u << t) - 1u));
            sa_n[slot] = t;
            sa_x0[slot] = x0; sa_x1r[slot] = x1r;
            sa_xs[slot] = max(x0, 0); sa_xe[slot] = min(x1 + 1, W_);
            sa_cls[slot] = c; sa_rx[slot] = rx;
            int inYm = (y >= ys) && (y < ye);
            sa_inYm[slot] = inYm;
            if (inYm) {
                float sy = __fsub_rn(
                    __fmul_rn(__fadd_rn(__fsub_rn((float)y, (float)y0), 0.5f), ry),
                    0.5f);
                sy = fminf(fmaxf(sy, 0.0f), 27.0f);
                float fiy0 = floorf(sy);
                int iy0 = (int)fiy0;
                int iy1 = min(iy0 + 1, ROI_ - 1);
                sa_wy[slot] = __fsub_rn(sy, fiy0);
                sa_r0[slot] = mskoff + iy0 * ROI_;
                sa_r1[slot] = mskoff + iy1 * ROI_;
            } else {
                sa_wy[slot] = 0.0f; sa_r0[slot] = 0; sa_r1[slot] = 0;
            }
        }
    }
    __syncthreads();

    const int K = sh_K;
    const float C_OUT = -0.0f;
    const float* semb0 = sem + (size_t)b * (C_ * H_ * W_) + (size_t)y * W_;

    for (int px = 0; px < W_ / 256; px++) {
        const int x = t + px * 256;

        // warp filter: instances whose strict x-interval meets this warp's
        // 32-pixel window
        unsigned wmask;
        {
            int wlo = px * 256 + (t & ~31);
            bool inter = false;
            if (lane < K) inter = (sa_x0[lane] <= wlo + 31) && (sa_x1r[lane] > wlo);
            wmask = __ballot_sync(0xffffffffu, inter);
        }

        float s[C_];
#pragma unroll
        for (int c = 0; c < C_; c++) s[c] = __ldg(semb0 + (size_t)c * (H_ * W_) + x);

        // fused argmax: stuff argmax (0..5) is a prefix of sem argmax (0..9)
        float best = s[0]; int bi = 0;
#pragma unroll
        for (int c = 1; c < NS_; c++) if (s[c] > best) { best = s[c]; bi = c; }
        float sb = best; int sem_pred = bi;
#pragma unroll
        for (int c = NS_; c < C_; c++) if (s[c] > sb) { sb = s[c]; sem_pred = c; }

        int nextn = 0;
        for (unsigned mrem = wmask; mrem; mrem &= mrem - 1) {
            int k = __ffs(mrem) - 1;
            int n = sa_n[k];
            if (n > nextn && best < 0.0f) { best = C_OUT; bi = NS_ + nextn; }
            nextn = n + 1;

            float v;
            bool sxin = (x >= sa_x0[k]) && (x < sa_x1r[k]);
            if (!sxin) {
                v = C_OUT;
            } else {
                float a = s[NS_ + sa_cls[k]];
                float m;
                bool mxin = sa_inYm[k] && (x >= sa_xs[k]) && (x < sa_xe[k]);
                if (mxin) {
                    float sx = __fsub_rn(
                        __fmul_rn(__fadd_rn(__fsub_rn((float)x, (float)sa_x0[k]), 0.5f),
                                  sa_rx[k]),
                        0.5f);
                    sx = fminf(fmaxf(sx, 0.0f), 27.0f);
                    float fix0 = floorf(sx);
                    int ix0 = (int)fix0;
                    int ix1 = min(ix0 + 1, ROI_ - 1);
                    float wx = __fsub_rn(sx, fix0);
                    const float* r0 = roi + sa_r0[k];
                    const float* r1 = roi + sa_r1[k];
                    float wy = sa_wy[k];
                    float omy = __fsub_rn(1.0f, wy);
                    float c0 = __fadd_rn(__fmul_rn(__ldg(r0 + ix0), omy),
                                         __fmul_rn(__ldg(r1 + ix0), wy));
                    float c1 = __fadd_rn(__fmul_rn(__ldg(r0 + ix1), omy),
                                         __fmul_rn(__ldg(r1 + ix1), wy));
                    float omx = __fsub_rn(1.0f, wx);
                    m = __fadd_rn(__fmul_rn(c0, omx), __fmul_rn(c1, wx));
                } else {
                    m = NEGV;
                }
                v = __fmul_rn(__fadd_rn(jsig(a), jsig(m)), __fadd_rn(a, m));
            }
            if (v > best) { best = v; bi = NS_ + n; }
        }
        if (nextn < N_ && best < 0.0f) { best = C_OUT; bi = NS_ + nextn; }

        g_pp[((size_t)b * H_ + y) * W_ + x] = (unsigned char)bi;

        // warp-aggregated histogram update
        int key = (bi >= NS_) ? (64 + (bi - NS_) * C_ + sem_pred) : bi;
        unsigned mm = __match_any_sync(0xffffffffu, key);
        if (lane == __ffs(mm) - 1) {
            int cnt = __popc(mm);
            if (key >= 64) atomicAdd(&sh_hist[key - 64], cnt);
            else           atomicAdd(&sh_cst[key], cnt);
        }
    }
    __syncthreads();

    for (int i = t; i < N_ * C_; i += 256) {
        int v = sh_hist[i];
        if (v) atomicAdd(&g_hist[b * N_ * C_ + i], v);
    }
    if (t < NS_) {
        int v = sh_cst[t];
        if (v) atomicAdd(&g_cstuff[b * NS_ + t], v);
    }
}

// ---- kernel 2: warp-parallel relabel + small outputs; self-cleans scratch --
__global__ void __launch_bounds__(64)
k_post(const int* __restrict__ cls, float* __restrict__ out, int out_size) {
    const unsigned FULL = 0xffffffffu;
    int b = threadIdx.x >> 5;
    int lane = threadIdx.x & 31;
    int* hist = g_hist + (b * N_ + lane) * C_;

    int tot = 0, mc = 0, smax = 0;
#pragma unroll
    for (int c = 0; c < C_; c++) {
        int h = hist[c];
        tot += h;
        if (h > mc) { mc = h; smax = c; }
    }
    int pres = (tot > 0);
    int tmp = cls[b * N_ + lane] + NS_;
    int br1 = (smax == tmp);
    int br2 = (!br1) && (2 * mc >= tot) && (smax < NS_) && pres;
    int semlab = br2 ? smax : tmp;
    int kept = pres && !br2;

    int sp[NS_];
#pragma unroll
    for (int c = 0; c < NS_; c++) {
        int v = (semlab == c) ? tot : 0;
#pragma unroll
        for (int off = 16; off; off >>= 1) v += __shfl_down_sync(FULL, v, off);
        v = __shfl_sync(FULL, v, 0);
        sp[c] = g_cstuff[b * NS_ + c] + v;
    }

    int srank[NS_], nst = 0;
#pragma unroll
    for (int c = 0; c < NS_; c++) { if (sp[c] > 0) nst++; srank[c] = nst - 1; }

    unsigned kb = __ballot_sync(FULL, kept);
    int rank_k = __popc(kb & ((1u << lane) - 1u));
    int rk = __popc(kb);

    float* lut = g_lutf + b * LUTN;
    if (lane < NS_) lut[lane] = (float)(srank[lane] + 1);
    int lv = kept ? (1 + nst + rank_k)
                  : ((semlab < NS_) ? (srank[semlab] + 1) : 0);
    lut[NS_ + lane] = (float)lv;

    if (out_size >= FULL_OUT) {
        float* pcls = out + SEAM_TOT + b * L_;
        float* pisc = out + SEAM_TOT + B_ * L_ + b * L_;
        pcls[lane] = -1.0f;
        if (lane < L_ - 32) pcls[32 + lane] = -1.0f;
        __syncwarp(FULL);
        if (lane == 0) pcls[0] = 255.0f;
        if (lane < NS_ && sp[lane] > 0) pcls[1 + srank[lane]] = (float)lane;
        if (kept) pcls[1 + nst + rank_k] = (float)tmp;
        int vl = 1 + nst + rk;
        pisc[lane] = (lane < vl) ? 0.0f : -1.0f;
        if (lane < L_ - 32) pisc[32 + lane] = ((32 + lane) < vl) ? 0.0f : -1.0f;
        if (lane == 0) out[SEAM_TOT + 2 * B_ * L_ + b] = (float)vl;
    }
    // zero any residual output beyond the defined region (usually empty loop)
    for (int i = FULL_OUT + threadIdx.x; i < out_size; i += 64) out[i] = 0.0f;

    // self-clean scratch for the next graph replay
#pragma unroll
    for (int c = 0; c < C_; c++) hist[c] = 0;
    if (lane < NS_) g_cstuff[b * NS_ + lane] = 0;
}

// ---- kernel 3: LUT remap; shared LUT, 1 quad/thread, 1152 blocks -----------
__global__ void __launch_bounds__(256)
k_out(float* __restrict__ out) {
    __shared__ float lut[B_ * LUTN];
    int t = threadIdx.x;
    if (t < B_ * LUTN) lut[t] = g_lutf[t];
    __syncthreads();
    int i = blockIdx.x * 256 + t;              // quad index
    const int HWQ = H_ * W_ / 4;
    unsigned int p = ((const unsigned int*)g_pp)[i];
    const float* l = lut + ((i >= HWQ) ? LUTN : 0);
    float4 o;
    o.x = l[p & 0xFF];
    o.y = l[(p >> 8) & 0xFF];
    o.z = l[(p >> 16) & 0xFF];
    o.w = l[(p >> 24) & 0xFF];
    ((float4*)out)[i] = o;
}

extern "C" void kernel_launch(void* const* d_in, const int* in_sizes, int n_in,
                              void* d_out, int out_size) {
    const float* sem = nullptr;
    const float* roi = nullptr;
    const float* bbx = nullptr;
    const int*   cls = nullptr;
    for (int i = 0; i < n_in; i++) {
        long long s = in_sizes[i];
        if (s >= 4000000)                 sem = (const float*)d_in[i];
        else if (s >= 100000)             roi = (const float*)d_in[i];
        else if (s >= 512 && s <= 4096)   bbx = (const float*)d_in[i];
        else if (s == 256) { if (!bbx) bbx = (const float*)d_in[i]; }
        else if (s <= 255)                cls = (const int*)d_in[i];
    }
    if (!sem) sem = (const float*)d_in[0];
    if (!roi) roi = (const float*)d_in[1];
    if (!bbx) bbx = (const float*)d_in[2];
    if (!cls) cls = (const int*)d_in[3];

    float* out = (float*)d_out;

    dim3 g1(H_, B_);
    k_main<<<g1, 256>>>(sem, roi, bbx, cls);
    k_post<<<1, 64>>>(cls, out, out_size);
    k_out<<<SEAM_TOT / 4 / 256, 256>>>(out);   // 1152 blocks
}